// round 3
// baseline (speedup 1.0000x reference)
#include <cuda_runtime.h>

#define CB 4
#define CS 2048
#define CD 1024
#define CH 16
#define CDH 64

// Scratch (static __device__ globals: the sanctioned no-alloc workaround).
__device__ float g_q[CB * CH * CS * CDH];   // (B,H,S,DH)
__device__ float g_k[CB * CH * CS * CDH];
__device__ float g_v[CB * CH * CS * CDH];
__device__ float g_o[CB * CS * CD];         // attention out, (B,S,D)

__device__ __forceinline__ float to_tf32(float x) {
    unsigned u;
    asm("cvt.rna.tf32.f32 %0, %1;" : "=r"(u) : "f"(x));
    return __uint_as_float(u);
}

__device__ __forceinline__ void mma_tf32(float c[4], unsigned a0, unsigned a1,
                                         unsigned a2, unsigned a3,
                                         unsigned b0, unsigned b1) {
    asm volatile(
        "mma.sync.aligned.m16n8k8.row.col.f32.tf32.tf32.f32 "
        "{%0,%1,%2,%3}, {%4,%5,%6,%7}, {%8,%9}, {%0,%1,%2,%3};\n"
        : "+f"(c[0]), "+f"(c[1]), "+f"(c[2]), "+f"(c[3])
        : "r"(a0), "r"(a1), "r"(a2), "r"(a3), "r"(b0), "r"(b1));
}

// ---------------------------------------------------------------------------
// tf32 tensor-core GEMM: Y = A(8192x1024) @ W(1024x1024) + bias.
// CTA tile 128x128, BK=16 double buffered, 8 warps as 2x4 grid of 64x32 warp
// tiles, mma.m16n8k8.tf32 (fp32 accum). Inputs rounded to tf32 with cvt.rna
// once on the global->smem path.
// LAYOUT 0: row-major out. LAYOUT 1: scatter to (B,H,S,DH).
// ---------------------------------------------------------------------------
template <int LAYOUT>
__device__ __forceinline__ void gemm_tf32(
    const float* __restrict__ A, const float* __restrict__ W,
    const float* __restrict__ bias, float* __restrict__ out)
{
    __shared__ float As[2][16][136];   // A^T tile: As[k][m], pad->conflict-free
    __shared__ float Bs[2][16][136];   // W tile:   Bs[k][n]

    const int tid = threadIdx.x;
    const int m0 = blockIdx.y * 128;
    const int n0 = blockIdx.x * 128;

    // Global-load assignments
    const int arow  = tid & 127;          // A row within tile
    const int acol  = (tid >> 7) * 8;     // 8 k's per thread (2 x float4)
    const int wkr   = tid >> 4;           // W k-row 0..15
    const int wnc   = (tid & 15) * 8;     // W n-col, 8 per thread

    const float* Ap = A + (size_t)(m0 + arow) * CD + acol;
    const float* Wp = W + (size_t)wkr * CD + n0 + wnc;

    // Preload ktile 0
    {
        float4 a0v = *(const float4*)(Ap);
        float4 a1v = *(const float4*)(Ap + 4);
        float4 b0v = *(const float4*)(Wp);
        float4 b1v = *(const float4*)(Wp + 4);
        As[0][acol + 0][arow] = to_tf32(a0v.x);
        As[0][acol + 1][arow] = to_tf32(a0v.y);
        As[0][acol + 2][arow] = to_tf32(a0v.z);
        As[0][acol + 3][arow] = to_tf32(a0v.w);
        As[0][acol + 4][arow] = to_tf32(a1v.x);
        As[0][acol + 5][arow] = to_tf32(a1v.y);
        As[0][acol + 6][arow] = to_tf32(a1v.z);
        As[0][acol + 7][arow] = to_tf32(a1v.w);
        float4 t0 = make_float4(to_tf32(b0v.x), to_tf32(b0v.y), to_tf32(b0v.z), to_tf32(b0v.w));
        float4 t1 = make_float4(to_tf32(b1v.x), to_tf32(b1v.y), to_tf32(b1v.z), to_tf32(b1v.w));
        *(float4*)&Bs[0][wkr][wnc]     = t0;
        *(float4*)&Bs[0][wkr][wnc + 4] = t1;
    }
    __syncthreads();

    const int wid    = tid >> 5;
    const int lane   = tid & 31;
    const int warp_m = (wid >> 2) * 64;   // 0 or 64
    const int warp_n = (wid & 3) * 32;    // 0,32,64,96
    const int g = lane >> 2;              // group 0..7
    const int t = lane & 3;               // thread-in-group

    float c[4][4][4];
#pragma unroll
    for (int mt = 0; mt < 4; mt++)
#pragma unroll
        for (int nt = 0; nt < 4; nt++)
#pragma unroll
            for (int r = 0; r < 4; r++) c[mt][nt][r] = 0.f;

    int buf = 0;
    for (int kt = 0; kt < 64; kt++) {
        float4 a0v, a1v, b0v, b1v;
        if (kt < 63) {
            a0v = *(const float4*)(Ap + (kt + 1) * 16);
            a1v = *(const float4*)(Ap + (kt + 1) * 16 + 4);
            b0v = *(const float4*)(Wp + (size_t)(kt + 1) * 16 * CD);
            b1v = *(const float4*)(Wp + (size_t)(kt + 1) * 16 * CD + 4);
        }
#pragma unroll
        for (int kc = 0; kc < 16; kc += 8) {
            unsigned a[4][4], b[4][2];
#pragma unroll
            for (int mt = 0; mt < 4; mt++) {
                const int m = warp_m + mt * 16 + g;
                a[mt][0] = __float_as_uint(As[buf][kc + t][m]);
                a[mt][1] = __float_as_uint(As[buf][kc + t][m + 8]);
                a[mt][2] = __float_as_uint(As[buf][kc + t + 4][m]);
                a[mt][3] = __float_as_uint(As[buf][kc + t + 4][m + 8]);
            }
#pragma unroll
            for (int nt = 0; nt < 4; nt++) {
                const int n = warp_n + nt * 8 + g;
                b[nt][0] = __float_as_uint(Bs[buf][kc + t][n]);
                b[nt][1] = __float_as_uint(Bs[buf][kc + t + 4][n]);
            }
#pragma unroll
            for (int mt = 0; mt < 4; mt++)
#pragma unroll
                for (int nt = 0; nt < 4; nt++)
                    mma_tf32(c[mt][nt], a[mt][0], a[mt][1], a[mt][2], a[mt][3],
                             b[nt][0], b[nt][1]);
        }
        if (kt < 63) {
            buf ^= 1;
            As[buf][acol + 0][arow] = to_tf32(a0v.x);
            As[buf][acol + 1][arow] = to_tf32(a0v.y);
            As[buf][acol + 2][arow] = to_tf32(a0v.z);
            As[buf][acol + 3][arow] = to_tf32(a0v.w);
            As[buf][acol + 4][arow] = to_tf32(a1v.x);
            As[buf][acol + 5][arow] = to_tf32(a1v.y);
            As[buf][acol + 6][arow] = to_tf32(a1v.z);
            As[buf][acol + 7][arow] = to_tf32(a1v.w);
            float4 t0 = make_float4(to_tf32(b0v.x), to_tf32(b0v.y), to_tf32(b0v.z), to_tf32(b0v.w));
            float4 t1 = make_float4(to_tf32(b1v.x), to_tf32(b1v.y), to_tf32(b1v.z), to_tf32(b1v.w));
            *(float4*)&Bs[buf][wkr][wnc]     = t0;
            *(float4*)&Bs[buf][wkr][wnc + 4] = t1;
        }
        __syncthreads();
    }

    // Epilogue: c0,c1 at (g, 2t/2t+1); c2,c3 at (g+8, ...)
#pragma unroll
    for (int mt = 0; mt < 4; mt++) {
#pragma unroll
        for (int nt = 0; nt < 4; nt++) {
            const int row = m0 + warp_m + mt * 16 + g;
            const int col = n0 + warp_n + nt * 8 + 2 * t;
            const float bx = bias[col], by = bias[col + 1];
            float2 r0 = make_float2(c[mt][nt][0] + bx, c[mt][nt][1] + by);
            float2 r1 = make_float2(c[mt][nt][2] + bx, c[mt][nt][3] + by);
            if (LAYOUT == 0) {
                *(float2*)&out[(size_t)row * CD + col]       = r0;
                *(float2*)&out[(size_t)(row + 8) * CD + col] = r1;
            } else {
                const int h = col >> 6, d = col & 63;
                {
                    const int b = row >> 11, s = row & 2047;
                    *(float2*)&out[(((size_t)(b * CH + h)) * CS + s) * CDH + d] = r0;
                }
                {
                    const int b = (row + 8) >> 11, s = (row + 8) & 2047;
                    *(float2*)&out[(((size_t)(b * CH + h)) * CS + s) * CDH + d] = r1;
                }
            }
        }
    }
}

__global__ __launch_bounds__(256) void proj_kernel(
    const float* __restrict__ x,
    const float* __restrict__ Wq, const float* __restrict__ bq,
    const float* __restrict__ Wk, const float* __restrict__ bk,
    const float* __restrict__ Wv, const float* __restrict__ bv)
{
    const float* W; const float* bias; float* out;
    if (blockIdx.z == 0)      { W = Wq; bias = bq; out = g_q; }
    else if (blockIdx.z == 1) { W = Wk; bias = bk; out = g_k; }
    else                      { W = Wv; bias = bv; out = g_v; }
    gemm_tf32<1>(x, W, bias, out);
}

__global__ __launch_bounds__(256) void outproj_kernel(
    const float* __restrict__ Wo, const float* __restrict__ bo,
    float* __restrict__ out)
{
    gemm_tf32<0>(g_o, Wo, bo, out);
}

// ---------------------------------------------------------------------------
// Attention (unchanged from passing R1 kernel). One block per (q-tile of 64,
// b*h). 256 threads as 16x16, 4x4 micro-tiles. Reproduces the reference
// recurrence EXACTLY (no final normalization); jb > qb blocks are exact
// identity updates -> skipped.
// ---------------------------------------------------------------------------
__global__ __launch_bounds__(256) void attn_kernel()
{
    __shared__ float Qt[64][64];   // Q^T, pre-scaled by 1/sqrt(DH): Qt[d][r]
    __shared__ float U[64][64];    // K^T during S-gemm (U[d][k]); then P[r][k]
    __shared__ float Vs[64][64];   // V natural: Vs[k][d]

    const int qb  = blockIdx.x;
    const int bh  = blockIdx.y;
    const int tid = threadIdx.x;
    const int tx  = tid & 15;
    const int ty  = tid >> 4;

    const size_t base = (size_t)bh * CS * CDH;
    const float* qp = g_q + base + (size_t)qb * 64 * CDH;

    {
        const int r  = tid >> 2;
        const int c0 = (tid & 3) * 16;
#pragma unroll
        for (int i = 0; i < 4; i++) {
            float4 t = *(const float4*)&qp[r * 64 + c0 + i * 4];
            Qt[c0 + i * 4 + 0][r] = t.x * 0.125f;
            Qt[c0 + i * 4 + 1][r] = t.y * 0.125f;
            Qt[c0 + i * 4 + 2][r] = t.z * 0.125f;
            Qt[c0 + i * 4 + 3][r] = t.w * 0.125f;
        }
    }

    float m_reg[4], l_reg[4], oacc[4][4];
#pragma unroll
    for (int i = 0; i < 4; i++) {
        m_reg[i] = -3.0e38f;
        l_reg[i] = 0.f;
#pragma unroll
        for (int j = 0; j < 4; j++) oacc[i][j] = 0.f;
    }

    for (int jb = 0; jb <= qb; jb++) {
        const float* kp = g_k + base + (size_t)jb * 64 * CDH;
        const float* vp = g_v + base + (size_t)jb * 64 * CDH;
        __syncthreads();
        {
            const int r  = tid >> 2;
            const int c0 = (tid & 3) * 16;
#pragma unroll
            for (int i = 0; i < 4; i++) {
                float4 t = *(const float4*)&kp[r * 64 + c0 + i * 4];
                U[c0 + i * 4 + 0][r] = t.x;
                U[c0 + i * 4 + 1][r] = t.y;
                U[c0 + i * 4 + 2][r] = t.z;
                U[c0 + i * 4 + 3][r] = t.w;
            }
#pragma unroll
            for (int i = 0; i < 4; i++) {
                const int off = tid * 4 + i * 1024;
                *(float4*)&(&Vs[0][0])[off] = *(const float4*)&vp[off];
            }
        }
        __syncthreads();

        float sv[4][4];
#pragma unroll
        for (int i = 0; i < 4; i++)
#pragma unroll
            for (int j = 0; j < 4; j++) sv[i][j] = 0.f;

#pragma unroll 8
        for (int d = 0; d < 64; d++) {
            float4 a = *(const float4*)&Qt[d][ty * 4];
            float4 b = *(const float4*)&U[d][tx * 4];
            const float ar[4] = {a.x, a.y, a.z, a.w};
            const float br[4] = {b.x, b.y, b.z, b.w};
#pragma unroll
            for (int i = 0; i < 4; i++)
#pragma unroll
                for (int j = 0; j < 4; j++)
                    sv[i][j] = fmaf(ar[i], br[j], sv[i][j]);
        }

        if (jb == qb) {
#pragma unroll
            for (int i = 0; i < 4; i++)
#pragma unroll
                for (int j = 0; j < 4; j++)
                    if (tx * 4 + j > ty * 4 + i) sv[i][j] = -3.0e38f;
        }
        __syncthreads();

        float f[4];
#pragma unroll
        for (int i = 0; i < 4; i++) {
            float mx = fmaxf(fmaxf(sv[i][0], sv[i][1]), fmaxf(sv[i][2], sv[i][3]));
#pragma unroll
            for (int o = 8; o >= 1; o >>= 1)
                mx = fmaxf(mx, __shfl_xor_sync(0xffffffffu, mx, o, 16));
            const float m_new = fmaxf(m_reg[i], mx);
            const float alpha = __expf(m_reg[i] - m_new);
            float p[4], rs = 0.f;
#pragma unroll
            for (int j = 0; j < 4; j++) { p[j] = __expf(sv[i][j] - m_new); rs += p[j]; }
#pragma unroll
            for (int o = 8; o >= 1; o >>= 1)
                rs += __shfl_xor_sync(0xffffffffu, rs, o, 16);
            const float l_new = alpha * l_reg[i] + rs;
            f[i] = alpha * l_reg[i] / l_new;
            m_reg[i] = m_new;
            l_reg[i] = l_new;
            *(float4*)&U[ty * 4 + i][tx * 4] = make_float4(p[0], p[1], p[2], p[3]);
        }
#pragma unroll
        for (int i = 0; i < 4; i++)
#pragma unroll
            for (int j = 0; j < 4; j++) oacc[i][j] *= f[i];
        __syncthreads();

#pragma unroll 8
        for (int kk = 0; kk < 64; kk++) {
            float4 b = *(const float4*)&Vs[kk][tx * 4];
            const float br[4] = {b.x, b.y, b.z, b.w};
            float ar[4];
#pragma unroll
            for (int i = 0; i < 4; i++) ar[i] = U[ty * 4 + i][kk];
#pragma unroll
            for (int i = 0; i < 4; i++)
#pragma unroll
                for (int j = 0; j < 4; j++)
                    oacc[i][j] = fmaf(ar[i], br[j], oacc[i][j]);
        }
    }

    const int b = bh >> 4, h = bh & 15;
#pragma unroll
    for (int i = 0; i < 4; i++) {
        const int sg = qb * 64 + ty * 4 + i;
        *(float4*)&g_o[((size_t)b * CS + sg) * CD + h * CDH + tx * 4] =
            make_float4(oacc[i][0], oacc[i][1], oacc[i][2], oacc[i][3]);
    }
}

// ---------------------------------------------------------------------------
extern "C" void kernel_launch(void* const* d_in, const int* in_sizes, int n_in,
                              void* d_out, int out_size)
{
    const float* x  = (const float*)d_in[0];
    const float* Wq = (const float*)d_in[1];
    const float* bq = (const float*)d_in[2];
    const float* Wk = (const float*)d_in[3];
    const float* bk = (const float*)d_in[4];
    const float* Wv = (const float*)d_in[5];
    const float* bv = (const float*)d_in[6];
    const float* Wo = (const float*)d_in[7];
    const float* bo = (const float*)d_in[8];
    float* out = (float*)d_out;

    dim3 gproj(CD / 128, (CB * CS) / 128, 3);   // 8 x 64 x 3
    proj_kernel<<<gproj, 256>>>(x, Wq, bq, Wk, bk, Wv, bv);

    dim3 gattn(CS / 64, CB * CH);               // 32 x 64
    attn_kernel<<<gattn, 256>>>();

    dim3 gout(CD / 128, (CB * CS) / 128);       // 8 x 64
    outproj_kernel<<<gout, 256>>>(Wo, bo, out);
}

// round 4
// speedup vs baseline: 1.2198x; 1.2198x over previous
#include <cuda_runtime.h>

#define CB 4
#define CS 2048
#define CD 1024
#define CH 16
#define CDH 64

// Scratch (static __device__ globals: the sanctioned no-alloc workaround).
__device__ float g_q[CB * CH * CS * CDH];   // (B,H,S,DH)
__device__ float g_k[CB * CH * CS * CDH];
__device__ float g_v[CB * CH * CS * CDH];
__device__ float g_o[CB * CS * CD];         // attention out, (B,S,D)

__device__ __forceinline__ float to_tf32(float x) {
    unsigned u;
    asm("cvt.rna.tf32.f32 %0, %1;" : "=r"(u) : "f"(x));
    return __uint_as_float(u);
}

__device__ __forceinline__ void mma_tf32(float c[4], unsigned a0, unsigned a1,
                                         unsigned a2, unsigned a3,
                                         unsigned b0, unsigned b1) {
    asm volatile(
        "mma.sync.aligned.m16n8k8.row.col.f32.tf32.tf32.f32 "
        "{%0,%1,%2,%3}, {%4,%5,%6,%7}, {%8,%9}, {%0,%1,%2,%3};\n"
        : "+f"(c[0]), "+f"(c[1]), "+f"(c[2]), "+f"(c[3])
        : "r"(a0), "r"(a1), "r"(a2), "r"(a3), "r"(b0), "r"(b1));
}

// ---------------------------------------------------------------------------
// tf32 tensor-core GEMM (unchanged from R3 passing kernel).
// ---------------------------------------------------------------------------
template <int LAYOUT>
__device__ __forceinline__ void gemm_tf32(
    const float* __restrict__ A, const float* __restrict__ W,
    const float* __restrict__ bias, float* __restrict__ out)
{
    __shared__ float As[2][16][136];
    __shared__ float Bs[2][16][136];

    const int tid = threadIdx.x;
    const int m0 = blockIdx.y * 128;
    const int n0 = blockIdx.x * 128;

    const int arow  = tid & 127;
    const int acol  = (tid >> 7) * 8;
    const int wkr   = tid >> 4;
    const int wnc   = (tid & 15) * 8;

    const float* Ap = A + (size_t)(m0 + arow) * CD + acol;
    const float* Wp = W + (size_t)wkr * CD + n0 + wnc;

    {
        float4 a0v = *(const float4*)(Ap);
        float4 a1v = *(const float4*)(Ap + 4);
        float4 b0v = *(const float4*)(Wp);
        float4 b1v = *(const float4*)(Wp + 4);
        As[0][acol + 0][arow] = to_tf32(a0v.x);
        As[0][acol + 1][arow] = to_tf32(a0v.y);
        As[0][acol + 2][arow] = to_tf32(a0v.z);
        As[0][acol + 3][arow] = to_tf32(a0v.w);
        As[0][acol + 4][arow] = to_tf32(a1v.x);
        As[0][acol + 5][arow] = to_tf32(a1v.y);
        As[0][acol + 6][arow] = to_tf32(a1v.z);
        As[0][acol + 7][arow] = to_tf32(a1v.w);
        float4 t0 = make_float4(to_tf32(b0v.x), to_tf32(b0v.y), to_tf32(b0v.z), to_tf32(b0v.w));
        float4 t1 = make_float4(to_tf32(b1v.x), to_tf32(b1v.y), to_tf32(b1v.z), to_tf32(b1v.w));
        *(float4*)&Bs[0][wkr][wnc]     = t0;
        *(float4*)&Bs[0][wkr][wnc + 4] = t1;
    }
    __syncthreads();

    const int wid    = tid >> 5;
    const int lane   = tid & 31;
    const int warp_m = (wid >> 2) * 64;
    const int warp_n = (wid & 3) * 32;
    const int g = lane >> 2;
    const int t = lane & 3;

    float c[4][4][4];
#pragma unroll
    for (int mt = 0; mt < 4; mt++)
#pragma unroll
        for (int nt = 0; nt < 4; nt++)
#pragma unroll
            for (int r = 0; r < 4; r++) c[mt][nt][r] = 0.f;

    int buf = 0;
    for (int kt = 0; kt < 64; kt++) {
        float4 a0v, a1v, b0v, b1v;
        if (kt < 63) {
            a0v = *(const float4*)(Ap + (kt + 1) * 16);
            a1v = *(const float4*)(Ap + (kt + 1) * 16 + 4);
            b0v = *(const float4*)(Wp + (size_t)(kt + 1) * 16 * CD);
            b1v = *(const float4*)(Wp + (size_t)(kt + 1) * 16 * CD + 4);
        }
#pragma unroll
        for (int kc = 0; kc < 16; kc += 8) {
            unsigned a[4][4], b[4][2];
#pragma unroll
            for (int mt = 0; mt < 4; mt++) {
                const int m = warp_m + mt * 16 + g;
                a[mt][0] = __float_as_uint(As[buf][kc + t][m]);
                a[mt][1] = __float_as_uint(As[buf][kc + t][m + 8]);
                a[mt][2] = __float_as_uint(As[buf][kc + t + 4][m]);
                a[mt][3] = __float_as_uint(As[buf][kc + t + 4][m + 8]);
            }
#pragma unroll
            for (int nt = 0; nt < 4; nt++) {
                const int n = warp_n + nt * 8 + g;
                b[nt][0] = __float_as_uint(Bs[buf][kc + t][n]);
                b[nt][1] = __float_as_uint(Bs[buf][kc + t + 4][n]);
            }
#pragma unroll
            for (int mt = 0; mt < 4; mt++)
#pragma unroll
                for (int nt = 0; nt < 4; nt++)
                    mma_tf32(c[mt][nt], a[mt][0], a[mt][1], a[mt][2], a[mt][3],
                             b[nt][0], b[nt][1]);
        }
        if (kt < 63) {
            buf ^= 1;
            As[buf][acol + 0][arow] = to_tf32(a0v.x);
            As[buf][acol + 1][arow] = to_tf32(a0v.y);
            As[buf][acol + 2][arow] = to_tf32(a0v.z);
            As[buf][acol + 3][arow] = to_tf32(a0v.w);
            As[buf][acol + 4][arow] = to_tf32(a1v.x);
            As[buf][acol + 5][arow] = to_tf32(a1v.y);
            As[buf][acol + 6][arow] = to_tf32(a1v.z);
            As[buf][acol + 7][arow] = to_tf32(a1v.w);
            float4 t0 = make_float4(to_tf32(b0v.x), to_tf32(b0v.y), to_tf32(b0v.z), to_tf32(b0v.w));
            float4 t1 = make_float4(to_tf32(b1v.x), to_tf32(b1v.y), to_tf32(b1v.z), to_tf32(b1v.w));
            *(float4*)&Bs[buf][wkr][wnc]     = t0;
            *(float4*)&Bs[buf][wkr][wnc + 4] = t1;
        }
        __syncthreads();
    }

#pragma unroll
    for (int mt = 0; mt < 4; mt++) {
#pragma unroll
        for (int nt = 0; nt < 4; nt++) {
            const int row = m0 + warp_m + mt * 16 + g;
            const int col = n0 + warp_n + nt * 8 + 2 * t;
            const float bx = bias[col], by = bias[col + 1];
            float2 r0 = make_float2(c[mt][nt][0] + bx, c[mt][nt][1] + by);
            float2 r1 = make_float2(c[mt][nt][2] + bx, c[mt][nt][3] + by);
            if (LAYOUT == 0) {
                *(float2*)&out[(size_t)row * CD + col]       = r0;
                *(float2*)&out[(size_t)(row + 8) * CD + col] = r1;
            } else {
                const int h = col >> 6, d = col & 63;
                {
                    const int b = row >> 11, s = row & 2047;
                    *(float2*)&out[(((size_t)(b * CH + h)) * CS + s) * CDH + d] = r0;
                }
                {
                    const int b = (row + 8) >> 11, s = (row + 8) & 2047;
                    *(float2*)&out[(((size_t)(b * CH + h)) * CS + s) * CDH + d] = r1;
                }
            }
        }
    }
}

__global__ __launch_bounds__(256) void proj_kernel(
    const float* __restrict__ x,
    const float* __restrict__ Wq, const float* __restrict__ bq,
    const float* __restrict__ Wk, const float* __restrict__ bk,
    const float* __restrict__ Wv, const float* __restrict__ bv)
{
    const float* W; const float* bias; float* out;
    if (blockIdx.z == 0)      { W = Wq; bias = bq; out = g_q; }
    else if (blockIdx.z == 1) { W = Wk; bias = bk; out = g_k; }
    else                      { W = Wv; bias = bv; out = g_v; }
    gemm_tf32<1>(x, W, bias, out);
}

__global__ __launch_bounds__(256) void outproj_kernel(
    const float* __restrict__ Wo, const float* __restrict__ bo,
    float* __restrict__ out)
{
    gemm_tf32<0>(g_o, Wo, bo, out);
}

// ---------------------------------------------------------------------------
// Tensor-core attention. One block per (q-tile of 64, b*h). 256 threads.
// S = QK^T via 3xTF32 (hi/lo split, near-fp32 exact). Softmax identical fp32
// math to the reference recurrence (no final normalization); jb > qb skipped.
// O += P@V via single tf32 (P,V rounded rna).
// MMA warp layout: 8 warps as 2(m) x 4(n), warp tile 32x16, m16n8k8.
// Softmax layout: 16x16 threads, 4 rows x 4 cols each (as in the R1 kernel).
// ---------------------------------------------------------------------------
struct AttnSmem {
    float Qh[64][68];
    float Ql[64][68];
    float Kh[64][68];
    float Kl[64][68];
    float Sp[64][68];   // S scores, then P (tf32-rounded) in place
    float Vs[64][72];   // V (tf32-rounded), padded 72 -> conflict-free B frags
    float fsm[64];      // per-row O rescale factor
};

__global__ __launch_bounds__(256) void attn_kernel()
{
    extern __shared__ char smem_raw[];
    AttnSmem* sm = (AttnSmem*)smem_raw;

    const int qb  = blockIdx.x;
    const int bh  = blockIdx.y;
    const int tid = threadIdx.x;
    // mma layout
    const int lane = tid & 31, wid = tid >> 5;
    const int g = lane >> 2, t = lane & 3;
    const int wm = (wid >> 2) * 32;       // 0 / 32
    const int wn = (wid & 3) * 16;        // 0,16,32,48
    // softmax layout
    const int tx = tid & 15, ty = tid >> 4;
    // loader layout
    const int lr = tid >> 2, lc = (tid & 3) * 16;

    const size_t base = (size_t)bh * CS * CDH;
    const float* qp = g_q + base + (size_t)qb * 64 * CDH;

    // Load Q (scaled by 1/sqrt(DH)=0.125) with hi/lo tf32 split.
#pragma unroll
    for (int i = 0; i < 4; i++) {
        float4 v = *(const float4*)&qp[lr * 64 + lc + i * 4];
        float xs[4] = {v.x * 0.125f, v.y * 0.125f, v.z * 0.125f, v.w * 0.125f};
#pragma unroll
        for (int j = 0; j < 4; j++) {
            float h = to_tf32(xs[j]);
            sm->Qh[lr][lc + i * 4 + j] = h;
            sm->Ql[lr][lc + i * 4 + j] = to_tf32(xs[j] - h);
        }
    }

    float m_reg[4], l_reg[4];
    float oc[2][2][4];
#pragma unroll
    for (int i = 0; i < 4; i++) { m_reg[i] = -3.0e38f; l_reg[i] = 0.f; }
#pragma unroll
    for (int mt = 0; mt < 2; mt++)
#pragma unroll
        for (int nt = 0; nt < 2; nt++)
#pragma unroll
            for (int r = 0; r < 4; r++) oc[mt][nt][r] = 0.f;

    for (int jb = 0; jb <= qb; jb++) {
        const float* kp = g_k + base + (size_t)jb * 64 * CDH;
        const float* vp = g_v + base + (size_t)jb * 64 * CDH;
        __syncthreads();   // prev iter done with K/V/Sp; Q visible after 1st

        // Load K hi/lo and V (rna tf32)
#pragma unroll
        for (int i = 0; i < 4; i++) {
            float4 v = *(const float4*)&kp[lr * 64 + lc + i * 4];
            float xs[4] = {v.x, v.y, v.z, v.w};
#pragma unroll
            for (int j = 0; j < 4; j++) {
                float h = to_tf32(xs[j]);
                sm->Kh[lr][lc + i * 4 + j] = h;
                sm->Kl[lr][lc + i * 4 + j] = to_tf32(xs[j] - h);
            }
            float4 vv = *(const float4*)&vp[lr * 64 + lc + i * 4];
            sm->Vs[lr][lc + i * 4 + 0] = to_tf32(vv.x);
            sm->Vs[lr][lc + i * 4 + 1] = to_tf32(vv.y);
            sm->Vs[lr][lc + i * 4 + 2] = to_tf32(vv.z);
            sm->Vs[lr][lc + i * 4 + 3] = to_tf32(vv.w);
        }
        __syncthreads();

        // ---- S = Q @ K^T, 3xTF32 ----
        float sc[2][2][4];
#pragma unroll
        for (int mt = 0; mt < 2; mt++)
#pragma unroll
            for (int nt = 0; nt < 2; nt++)
#pragma unroll
                for (int r = 0; r < 4; r++) sc[mt][nt][r] = 0.f;

#pragma unroll
        for (int kc = 0; kc < 64; kc += 8) {
            unsigned ah[2][4], al[2][4], bhf[2][2], blf[2][2];
#pragma unroll
            for (int mt = 0; mt < 2; mt++) {
                const int m = wm + mt * 16 + g;
                ah[mt][0] = __float_as_uint(sm->Qh[m][kc + t]);
                ah[mt][1] = __float_as_uint(sm->Qh[m + 8][kc + t]);
                ah[mt][2] = __float_as_uint(sm->Qh[m][kc + t + 4]);
                ah[mt][3] = __float_as_uint(sm->Qh[m + 8][kc + t + 4]);
                al[mt][0] = __float_as_uint(sm->Ql[m][kc + t]);
                al[mt][1] = __float_as_uint(sm->Ql[m + 8][kc + t]);
                al[mt][2] = __float_as_uint(sm->Ql[m][kc + t + 4]);
                al[mt][3] = __float_as_uint(sm->Ql[m + 8][kc + t + 4]);
            }
#pragma unroll
            for (int nt = 0; nt < 2; nt++) {
                const int n = wn + nt * 8 + g;
                bhf[nt][0] = __float_as_uint(sm->Kh[n][kc + t]);
                bhf[nt][1] = __float_as_uint(sm->Kh[n][kc + t + 4]);
                blf[nt][0] = __float_as_uint(sm->Kl[n][kc + t]);
                blf[nt][1] = __float_as_uint(sm->Kl[n][kc + t + 4]);
            }
#pragma unroll
            for (int mt = 0; mt < 2; mt++)
#pragma unroll
                for (int nt = 0; nt < 2; nt++) {
                    mma_tf32(sc[mt][nt], ah[mt][0], ah[mt][1], ah[mt][2], ah[mt][3],
                             bhf[nt][0], bhf[nt][1]);
                    mma_tf32(sc[mt][nt], ah[mt][0], ah[mt][1], ah[mt][2], ah[mt][3],
                             blf[nt][0], blf[nt][1]);
                    mma_tf32(sc[mt][nt], al[mt][0], al[mt][1], al[mt][2], al[mt][3],
                             bhf[nt][0], bhf[nt][1]);
                }
        }
        // Write S fragments to smem
#pragma unroll
        for (int mt = 0; mt < 2; mt++)
#pragma unroll
            for (int nt = 0; nt < 2; nt++) {
                const int row = wm + mt * 16 + g;
                const int col = wn + nt * 8 + 2 * t;
                sm->Sp[row][col]         = sc[mt][nt][0];
                sm->Sp[row][col + 1]     = sc[mt][nt][1];
                sm->Sp[row + 8][col]     = sc[mt][nt][2];
                sm->Sp[row + 8][col + 1] = sc[mt][nt][3];
            }
        __syncthreads();

        // ---- softmax / recurrence (exact reference math, fp32) ----
#pragma unroll
        for (int i = 0; i < 4; i++) {
            const int row = ty * 4 + i;
            float s[4];
#pragma unroll
            for (int j = 0; j < 4; j++) {
                s[j] = sm->Sp[row][tx * 4 + j];
                if (jb == qb && (tx * 4 + j) > row) s[j] = -3.0e38f;
            }
            float mx = fmaxf(fmaxf(s[0], s[1]), fmaxf(s[2], s[3]));
#pragma unroll
            for (int o = 8; o >= 1; o >>= 1)
                mx = fmaxf(mx, __shfl_xor_sync(0xffffffffu, mx, o, 16));
            const float m_new = fmaxf(m_reg[i], mx);
            const float alpha = __expf(m_reg[i] - m_new);
            float p[4], rs = 0.f;
#pragma unroll
            for (int j = 0; j < 4; j++) { p[j] = __expf(s[j] - m_new); rs += p[j]; }
#pragma unroll
            for (int o = 8; o >= 1; o >>= 1)
                rs += __shfl_xor_sync(0xffffffffu, rs, o, 16);
            const float l_new = alpha * l_reg[i] + rs;
            const float f = alpha * l_reg[i] / l_new;   // 0 on first live block
            m_reg[i] = m_new;
            l_reg[i] = l_new;
#pragma unroll
            for (int j = 0; j < 4; j++)
                sm->Sp[row][tx * 4 + j] = to_tf32(p[j]);
            if (tx == 0) sm->fsm[row] = f;
        }
        __syncthreads();

        // ---- O = O * f + P @ V ----
#pragma unroll
        for (int mt = 0; mt < 2; mt++) {
            const float f0 = sm->fsm[wm + mt * 16 + g];
            const float f1 = sm->fsm[wm + mt * 16 + g + 8];
#pragma unroll
            for (int nt = 0; nt < 2; nt++) {
                oc[mt][nt][0] *= f0; oc[mt][nt][1] *= f0;
                oc[mt][nt][2] *= f1; oc[mt][nt][3] *= f1;
            }
        }
#pragma unroll
        for (int kc = 0; kc < 64; kc += 8) {
            unsigned a[2][4], b[2][2];
#pragma unroll
            for (int mt = 0; mt < 2; mt++) {
                const int m = wm + mt * 16 + g;
                a[mt][0] = __float_as_uint(sm->Sp[m][kc + t]);
                a[mt][1] = __float_as_uint(sm->Sp[m + 8][kc + t]);
                a[mt][2] = __float_as_uint(sm->Sp[m][kc + t + 4]);
                a[mt][3] = __float_as_uint(sm->Sp[m + 8][kc + t + 4]);
            }
#pragma unroll
            for (int nt = 0; nt < 2; nt++) {
                const int n = wn + nt * 8 + g;
                b[nt][0] = __float_as_uint(sm->Vs[kc + t][n]);
                b[nt][1] = __float_as_uint(sm->Vs[kc + t + 4][n]);
            }
#pragma unroll
            for (int mt = 0; mt < 2; mt++)
#pragma unroll
                for (int nt = 0; nt < 2; nt++)
                    mma_tf32(oc[mt][nt], a[mt][0], a[mt][1], a[mt][2], a[mt][3],
                             b[nt][0], b[nt][1]);
        }
    }

    // Write O to g_o (B,S,D): row = qb*64 + ..., col = h*64 + ...
    const int b = bh >> 4, h = bh & 15;
#pragma unroll
    for (int mt = 0; mt < 2; mt++)
#pragma unroll
        for (int nt = 0; nt < 2; nt++) {
            const int row = qb * 64 + wm + mt * 16 + g;
            const int col = h * 64 + wn + nt * 8 + 2 * t;
            *(float2*)&g_o[((size_t)b * CS + row) * CD + col] =
                make_float2(oc[mt][nt][0], oc[mt][nt][1]);
            *(float2*)&g_o[((size_t)b * CS + row + 8) * CD + col] =
                make_float2(oc[mt][nt][2], oc[mt][nt][3]);
        }
}

// ---------------------------------------------------------------------------
extern "C" void kernel_launch(void* const* d_in, const int* in_sizes, int n_in,
                              void* d_out, int out_size)
{
    const float* x  = (const float*)d_in[0];
    const float* Wq = (const float*)d_in[1];
    const float* bq = (const float*)d_in[2];
    const float* Wk = (const float*)d_in[3];
    const float* bk = (const float*)d_in[4];
    const float* Wv = (const float*)d_in[5];
    const float* bv = (const float*)d_in[6];
    const float* Wo = (const float*)d_in[7];
    const float* bo = (const float*)d_in[8];
    float* out = (float*)d_out;

    dim3 gproj(CD / 128, (CB * CS) / 128, 3);   // 8 x 64 x 3
    proj_kernel<<<gproj, 256>>>(x, Wq, bq, Wk, bk, Wv, bv);

    static const size_t attn_smem = sizeof(AttnSmem);
    cudaFuncSetAttribute(attn_kernel, cudaFuncAttributeMaxDynamicSharedMemorySize,
                         (int)attn_smem);
    dim3 gattn(CS / 64, CB * CH);               // 32 x 64
    attn_kernel<<<gattn, 256, attn_smem>>>();

    dim3 gout(CD / 128, (CB * CS) / 128);       // 8 x 64
    outproj_kernel<<<gout, 256>>>(Wo, bo, out);
}